// round 14
// baseline (speedup 1.0000x reference)
#include <cuda_runtime.h>
#include <cuda_fp16.h>
#include <cstdint>

// PointPairNet: B=4, N=512, D=3. pair-relu(64) -> 64 -> 128, global max-pool, head MLP.
// R13: single fused persistent kernel (phaseA layer1 -> grid barrier -> R12 tile loop with
// private partial-max slots -> last-CTA reduction + head MLP). One launch per call.

#define BATCH 4
#define NPTS  512
#define GRID  148
#define NTILES 4096         // 256-pair tiles: 4 batches x 128 i-groups x 8 j-groups

__device__ float    g_Ai[BATCH * NPTS * 64];
__device__ float    g_Aj[BATCH * NPTS * 64];
__device__ float    g_part[GRID * BATCH * 128];   // per-CTA partial maxes (fully rewritten每 call)
__device__ unsigned g_entry;                       // grid barrier counter (reset by last CTA)
__device__ unsigned g_done;                        // completion counter  (reset by last CTA)

// ---------------- helpers ----------------
static __device__ __forceinline__ uint32_t smem_u32(const void* p) {
    uint32_t a;
    asm("{ .reg .u64 t; cvta.to.shared.u64 t, %1; cvt.u32.u64 %0, t; }" : "=r"(a) : "l"(p));
    return a;
}
static __device__ __forceinline__ uint32_t cvt2h(float f0, float f1) {
    __half2 h = __floats2half2_rn(f0, f1);
    return *reinterpret_cast<uint32_t*>(&h);
}

#define LDSM_X4(r0, r1, r2, r3, a)                                                  \
    asm volatile("ldmatrix.sync.aligned.m8n8.x4.shared.b16 {%0,%1,%2,%3}, [%4];"    \
                 : "=r"(r0), "=r"(r1), "=r"(r2), "=r"(r3) : "r"(a))
#define LDSM_X4T(r0, r1, r2, r3, a)                                                 \
    asm volatile("ldmatrix.sync.aligned.m8n8.x4.trans.shared.b16 {%0,%1,%2,%3}, [%4];" \
                 : "=r"(r0), "=r"(r1), "=r"(r2), "=r"(r3) : "r"(a))

static __device__ __forceinline__ void mma_f16(float* c, const uint32_t* a,
                                               uint32_t b0, uint32_t b1) {
    asm volatile("mma.sync.aligned.m16n8k16.row.col.f32.f16.f16.f32 "
                 "{%0,%1,%2,%3}, {%4,%5,%6,%7}, {%8,%9}, {%0,%1,%2,%3};"
                 : "+f"(c[0]), "+f"(c[1]), "+f"(c[2]), "+f"(c[3])
                 : "r"(a[0]), "r"(a[1]), "r"(a[2]), "r"(a[3]), "r"(b0), "r"(b1));
}

// ---------------- SMEM layout (bytes) ----------------
#define SM_B2    0          // 64 floats
#define SM_W2    256        // [k=64][n=64] fp16, stride 144 -> 9216
#define SM_W3    9472       // [k=64][n=128] fp16, stride 272 -> 17408
#define SM_H1A   26880      // [row=256][k=64] fp16, stride 144 -> 36864 (buffer 0)
#define SM_H1B   63744      // buffer 1
#define SM_RED   100608     // flush scratch: 8 warps x 128 floats = 4096 B (tail reuses)
#define SM_FLAG  104704     // 16 B (last-CTA flag)
#define SMEM_BYTES 104768

// ---------------- fused persistent kernel ----------------
__global__ void __launch_bounds__(256, 1)
k_all(const float* __restrict__ X,  const float* __restrict__ W1,
      const float* __restrict__ b1, const float* __restrict__ W2,
      const float* __restrict__ b2, const float* __restrict__ W3,
      const float* __restrict__ b3, const float* __restrict__ F1,
      const float* __restrict__ bf1, const float* __restrict__ F2,
      const float* __restrict__ bf2, float* __restrict__ out) {
    extern __shared__ char smem[];
    const uint32_t smb = smem_u32(smem);
    float* smf = reinterpret_cast<float*>(smem);
    int* sFlag = reinterpret_cast<int*>(smem + SM_FLAG);
    const int tid  = threadIdx.x;
    const int wid  = tid >> 5;
    const int lane = tid & 31;
    const int tig  = lane & 3;

    // ---- phase A: distributed layer-1 split (was k_pre) ----
    for (int idx = tid; idx < 14 * 64; idx += 256) {
        int k = idx >> 6, c = idx & 63;
        int ng = blockIdx.x + GRID * k;
        if (ng < BATCH * NPTS) {
            float x0 = X[ng * 3 + 0], x1 = X[ng * 3 + 1], x2 = X[ng * 3 + 2];
            const float* w = W1 + c * 6;
            g_Aj[ng * 64 + c] = x0 * w[0] + x1 * w[1] + x2 * w[2];
            g_Ai[ng * 64 + c] = b1[c] + x0 * w[3] + x1 * w[4] + x2 * w[5];
        }
    }

    // ---- stage weights (smem, CTA-local; overlaps phase A) ----
    for (int i2 = tid; i2 < 2048; i2 += 256) {           // W2: 64n x 64k
        int k = i2 >> 5, np = i2 & 31;
        *reinterpret_cast<uint32_t*>(smem + SM_W2 + k * 144 + np * 4) =
            cvt2h(W2[(2 * np) * 64 + k], W2[(2 * np + 1) * 64 + k]);
    }
    for (int i2 = tid; i2 < 4096; i2 += 256) {           // W3: 128n x 64k
        int k = i2 >> 6, np = i2 & 63;
        *reinterpret_cast<uint32_t*>(smem + SM_W3 + k * 272 + np * 4) =
            cvt2h(W3[(2 * np) * 64 + k], W3[(2 * np + 1) * 64 + k]);
    }
    if (tid < 64) smf[SM_B2 / 4 + tid] = b2[tid];

    // ---- grid barrier: all CTAs co-resident (1 CTA/SM by smem) ----
    __threadfence();
    __syncthreads();
    if (tid == 0) {
        atomicAdd(&g_entry, 1u);
        while (*reinterpret_cast<volatile unsigned*>(&g_entry) < (unsigned)gridDim.x) { }
    }
    __syncthreads();

    // per-lane ldmatrix base addresses (two H1 buffers; rowset s at +s*128*144)
    const int rowA = (wid << 4) + (lane & 7) + ((lane >> 3) & 1) * 8;
    const uint32_t aA0 = smb + SM_H1A + rowA * 144 + ((lane >> 4) << 4);
    const uint32_t aA1 = smb + SM_H1B + rowA * 144 + ((lane >> 4) << 4);
    const int krow = (lane & 7) + ((lane >> 3) & 1) * 8;
    const uint32_t aW2 = smb + SM_W2 + krow * 144 + ((lane >> 4) << 4);
    const uint32_t aW3 = smb + SM_W3 + krow * 272 + ((lane >> 4) << 4);

    // H1 build indices: one full row (64 k) per thread
    const int b_il = tid >> 6;              // i_local 0..3
    const int b_jl = tid & 63;              // j_local

    auto build = [&](int tt, int hoff) {
        const int bb = tt >> 10, itt = (tt >> 3) & 127, jtt = tt & 7;
        const float4* ajp = reinterpret_cast<const float4*>(
            g_Aj + ((bb * NPTS + jtt * 64 + b_jl) * 64));
        const float4* aip = reinterpret_cast<const float4*>(
            g_Ai + ((bb * NPTS + itt * 4 + b_il) * 64));
        uint4* dh = reinterpret_cast<uint4*>(smem + hoff + tid * 144);
#pragma unroll
        for (int u = 0; u < 4; u++) {
            float4 a0 = ajp[4 * u + 0], i0 = aip[4 * u + 0];
            float4 a1 = ajp[4 * u + 1], i1 = aip[4 * u + 1];
            float4 a2v = ajp[4 * u + 2], i2v = aip[4 * u + 2];
            float4 a3 = ajp[4 * u + 3], i3 = aip[4 * u + 3];
            uint4 d;
            d.x = cvt2h(fmaxf(a0.x + i0.x, 0.f), fmaxf(a0.y + i0.y, 0.f));
            d.y = cvt2h(fmaxf(a0.z + i0.z, 0.f), fmaxf(a0.w + i0.w, 0.f));
            d.z = cvt2h(fmaxf(a1.x + i1.x, 0.f), fmaxf(a1.y + i1.y, 0.f));
            d.w = cvt2h(fmaxf(a1.z + i1.z, 0.f), fmaxf(a1.w + i1.w, 0.f));
            dh[2 * u] = d;
            uint4 e;
            e.x = cvt2h(fmaxf(a2v.x + i2v.x, 0.f), fmaxf(a2v.y + i2v.y, 0.f));
            e.y = cvt2h(fmaxf(a2v.z + i2v.z, 0.f), fmaxf(a2v.w + i2v.w, 0.f));
            e.z = cvt2h(fmaxf(a3.x + i3.x, 0.f), fmaxf(a3.y + i3.y, 0.f));
            e.w = cvt2h(fmaxf(a3.z + i3.z, 0.f), fmaxf(a3.w + i3.w, 0.f));
            dh[2 * u + 1] = e;
        }
    };

    float maxv[32];
#pragma unroll
    for (int q = 0; q < 32; q++) maxv[q] = -3.4e38f;
    int cur_b = -1;

    // flush maxv for batch bflush into this CTA's private slot (uniform call sites only)
    auto flush = [&](int bflush) {
#pragma unroll
        for (int q = 0; q < 32; q++) {
            float v = maxv[q];
            v = fmaxf(v, __shfl_xor_sync(0xffffffffu, v, 4));
            v = fmaxf(v, __shfl_xor_sync(0xffffffffu, v, 8));
            v = fmaxf(v, __shfl_xor_sync(0xffffffffu, v, 16));
            if (lane < 4)
                smf[SM_RED / 4 + wid * 128 + (q >> 1) * 8 + 2 * lane + (q & 1)] = v;
            maxv[q] = -3.4e38f;
        }
        __syncthreads();
        if (tid < 128) {
            float m = smf[SM_RED / 4 + tid];
#pragma unroll
            for (int w = 1; w < 8; w++) m = fmaxf(m, smf[SM_RED / 4 + w * 128 + tid]);
            g_part[(blockIdx.x * BATCH + bflush) * 128 + tid] = m;
        }
        __syncthreads();
    };

    // ---- prologue ----
    int t0 = blockIdx.x;
    if (t0 < NTILES) build(t0, SM_H1A);
    __syncthreads();                 // tile t0 H1 ready

    int buf = 0;
    for (int t = t0; t < NTILES; t += gridDim.x) {
        const int b = t >> 10;
        if (b != cur_b) {
            if (cur_b >= 0) flush(cur_b);
            cur_b = b;
        }

        // ---- load A1 fragments: 2 rowsets x 4 kt ----
        const uint32_t aA = buf ? aA1 : aA0;
        uint32_t a1[2][16];
#pragma unroll
        for (int s = 0; s < 2; s++)
#pragma unroll
            for (int kt = 0; kt < 4; kt++)
                LDSM_X4(a1[s][4 * kt], a1[s][4 * kt + 1], a1[s][4 * kt + 2], a1[s][4 * kt + 3],
                        aA + s * (128 * 144) + kt * 32);

        // ---- pipelined: build NEXT tile into the other buffer ----
        const int tn = t + gridDim.x;
        if (tn < NTILES) build(tn, buf ? SM_H1A : SM_H1B);

        // ---- GEMM1: C1[2][16 x 64] = H1 x W2^T; one weight load feeds 4 MMAs ----
        float c1[2][8][4];
#pragma unroll
        for (int nt = 0; nt < 8; nt++) {
            float bl = smf[SM_B2 / 4 + nt * 8 + 2 * tig];
            float bh = smf[SM_B2 / 4 + nt * 8 + 2 * tig + 1];
#pragma unroll
            for (int s = 0; s < 2; s++) {
                c1[s][nt][0] = bl; c1[s][nt][1] = bh; c1[s][nt][2] = bl; c1[s][nt][3] = bh;
            }
        }
#pragma unroll
        for (int kt = 0; kt < 4; kt++) {
#pragma unroll
            for (int p = 0; p < 4; p++) {
                uint32_t bh0, bh1, bh2, bh3;
                LDSM_X4T(bh0, bh1, bh2, bh3, aW2 + kt * 2304 + p * 32);
#pragma unroll
                for (int s = 0; s < 2; s++) {
                    mma_f16(c1[s][2 * p],     &a1[s][4 * kt], bh0, bh1);
                    mma_f16(c1[s][2 * p + 1], &a1[s][4 * kt], bh2, bh3);
                }
            }
        }

        // ---- epilogue1: H2 = relu(C1); repack -> A2-frags ----
        uint32_t a2[2][16];
#pragma unroll
        for (int s = 0; s < 2; s++)
#pragma unroll
            for (int kt2 = 0; kt2 < 4; kt2++) {
                const int na = 2 * kt2, nb = 2 * kt2 + 1;
                a2[s][4 * kt2 + 0] = cvt2h(fmaxf(c1[s][na][0], 0.f), fmaxf(c1[s][na][1], 0.f));
                a2[s][4 * kt2 + 1] = cvt2h(fmaxf(c1[s][na][2], 0.f), fmaxf(c1[s][na][3], 0.f));
                a2[s][4 * kt2 + 2] = cvt2h(fmaxf(c1[s][nb][0], 0.f), fmaxf(c1[s][nb][1], 0.f));
                a2[s][4 * kt2 + 3] = cvt2h(fmaxf(c1[s][nb][2], 0.f), fmaxf(c1[s][nb][3], 0.f));
            }

        // ---- GEMM2: D3 = H2 x W3^T, two n-halves ----
#pragma unroll
        for (int h = 0; h < 2; h++) {
            float d3[2][8][4];
#pragma unroll
            for (int s = 0; s < 2; s++)
#pragma unroll
                for (int nt = 0; nt < 8; nt++)
#pragma unroll
                    for (int q = 0; q < 4; q++) d3[s][nt][q] = 0.f;
#pragma unroll
            for (int kt2 = 0; kt2 < 4; kt2++) {
#pragma unroll
                for (int p = 0; p < 4; p++) {
                    uint32_t bh0, bh1, bh2, bh3;
                    LDSM_X4T(bh0, bh1, bh2, bh3, aW3 + kt2 * 4352 + (h * 4 + p) * 32);
#pragma unroll
                    for (int s = 0; s < 2; s++) {
                        mma_f16(d3[s][2 * p],     &a2[s][4 * kt2], bh0, bh1);
                        mma_f16(d3[s][2 * p + 1], &a2[s][4 * kt2], bh2, bh3);
                    }
                }
            }
#pragma unroll
            for (int nt = 0; nt < 8; nt++) {
                float m0 = fmaxf(fmaxf(d3[0][nt][0], d3[0][nt][2]),
                                 fmaxf(d3[1][nt][0], d3[1][nt][2]));
                float m1 = fmaxf(fmaxf(d3[0][nt][1], d3[0][nt][3]),
                                 fmaxf(d3[1][nt][1], d3[1][nt][3]));
                maxv[h * 16 + 2 * nt]     = fmaxf(maxv[h * 16 + 2 * nt],     m0);
                maxv[h * 16 + 2 * nt + 1] = fmaxf(maxv[h * 16 + 2 * nt + 1], m1);
            }
        }

        __syncthreads();
        buf ^= 1;
    }
    flush(cur_b);                    // every CTA has tiles in every batch; cur_b >= 0

    // ---- completion: last CTA reduces partials + head MLP ----
    __threadfence();
    __syncthreads();
    if (tid == 0) sFlag[0] = (atomicAdd(&g_done, 1u) == (unsigned)gridDim.x - 1) ? 1 : 0;
    __syncthreads();

    if (sFlag[0]) {
        __threadfence();
        // reduce 148 partials -> pooled P + b3 into smem sp[4][128]
        for (int pair = tid; pair < BATCH * 128; pair += 256) {
            int bb = pair >> 7, ch = pair & 127;
            float m = -3.4e38f;
            for (int c = 0; c < (int)gridDim.x; c++)
                m = fmaxf(m, g_part[(c * BATCH + bb) * 128 + ch]);
            smf[SM_RED / 4 + pair] = m + b3[ch];
        }
        __syncthreads();
        // head MLP per batch (sp at SM_RED, st at SM_RED + 2048B)
        float* st = smf + SM_RED / 4 + 512;
        for (int bb = 0; bb < BATCH; bb++) {
            const int r = tid >> 2, q = tid & 3;
            float a = 0.f;
            const float* fr = F1 + r * 128 + q * 32;
            const float* spb = smf + SM_RED / 4 + bb * 128 + q * 32;
#pragma unroll 8
            for (int c = 0; c < 32; c++) a += fr[c] * spb[c];
            a += __shfl_xor_sync(0xffffffffu, a, 1);
            a += __shfl_xor_sync(0xffffffffu, a, 2);
            if (q == 0) st[r] = fmaxf(a + bf1[r], 0.f);
            __syncthreads();
            if (tid < 2) {
                float acc = bf2[tid];
#pragma unroll
                for (int j = 0; j < 64; j++) acc += F2[tid * 64 + j] * st[j];
                out[bb * 2 + tid] = acc;
            }
            __syncthreads();
        }
        if (tid == 0) { g_done = 0; g_entry = 0; __threadfence(); }
    }
}

// ---------------- launch ----------------
extern "C" void kernel_launch(void* const* d_in, const int* in_sizes, int n_in,
                              void* d_out, int out_size) {
    const float* X   = (const float*)d_in[0];
    const float* W1  = (const float*)d_in[1];
    const float* b1  = (const float*)d_in[2];
    const float* W2  = (const float*)d_in[3];
    const float* b2  = (const float*)d_in[4];
    const float* W3  = (const float*)d_in[5];
    const float* b3  = (const float*)d_in[6];
    const float* F1  = (const float*)d_in[7];
    const float* bf1 = (const float*)d_in[8];
    const float* F2  = (const float*)d_in[9];
    const float* bf2 = (const float*)d_in[10];
    float* out = (float*)d_out;

    cudaFuncSetAttribute(k_all, cudaFuncAttributeMaxDynamicSharedMemorySize, SMEM_BYTES);

    k_all<<<GRID, 256, SMEM_BYTES>>>(X, W1, b1, W2, b2, W3,
                                     b3, F1, bf1, F2, bf2, out);
}

// round 16
// speedup vs baseline: 1.0372x; 1.0372x over previous
#include <cuda_runtime.h>
#include <cuda_fp16.h>
#include <cstdint>

// PointPairNet: B=4, N=512, D=3. pair-relu(64) -> 64 -> 128, global max-pool, head MLP.
// R14: fused persistent kernel; weights in [n][k] layout -> non-trans ldmatrix B-frags;
// W2 fragments register-resident (zero weight LDSM in GEMM1).

#define BATCH 4
#define NPTS  512
#define GRID  148
#define NTILES 4096         // 256-pair tiles: 4 batches x 128 i-groups x 8 j-groups

__device__ float    g_Ai[BATCH * NPTS * 64];
__device__ float    g_Aj[BATCH * NPTS * 64];
__device__ float    g_part[GRID * BATCH * 128];   // per-CTA partial maxes (fully rewritten per call)
__device__ unsigned g_entry;                       // grid barrier counter (reset by last CTA)
__device__ unsigned g_done;                        // completion counter  (reset by last CTA)

// ---------------- helpers ----------------
static __device__ __forceinline__ uint32_t smem_u32(const void* p) {
    uint32_t a;
    asm("{ .reg .u64 t; cvta.to.shared.u64 t, %1; cvt.u32.u64 %0, t; }" : "=r"(a) : "l"(p));
    return a;
}
static __device__ __forceinline__ uint32_t cvt2h(float f0, float f1) {
    __half2 h = __floats2half2_rn(f0, f1);
    return *reinterpret_cast<uint32_t*>(&h);
}

#define LDSM_X4(r0, r1, r2, r3, a)                                                  \
    asm volatile("ldmatrix.sync.aligned.m8n8.x4.shared.b16 {%0,%1,%2,%3}, [%4];"    \
                 : "=r"(r0), "=r"(r1), "=r"(r2), "=r"(r3) : "r"(a))

static __device__ __forceinline__ void mma_f16(float* c, const uint32_t* a,
                                               uint32_t b0, uint32_t b1) {
    asm volatile("mma.sync.aligned.m16n8k16.row.col.f32.f16.f16.f32 "
                 "{%0,%1,%2,%3}, {%4,%5,%6,%7}, {%8,%9}, {%0,%1,%2,%3};"
                 : "+f"(c[0]), "+f"(c[1]), "+f"(c[2]), "+f"(c[3])
                 : "r"(a[0]), "r"(a[1]), "r"(a[2]), "r"(a[3]), "r"(b0), "r"(b1));
}

// ---------------- SMEM layout (bytes) ----------------
// All weight/activation rows stride 144 B (16B-aligned, conflict-free 8-row ldmatrix).
#define SM_B2    0          // 64 floats (256B)
#define SM_W2    256        // [n=64][k=64] fp16, stride 144 -> 9216
#define SM_W3    9472       // [n=128][k=64] fp16, stride 144 -> 18432
#define SM_H1A   27904      // [row=256][k=64] fp16, stride 144 -> 36864 (buffer 0)
#define SM_H1B   64768      // buffer 1
#define SM_RED   101632     // flush scratch: 8 warps x 128 floats = 4096 B (tail reuses)
#define SM_FLAG  105728     // 64 B (last-CTA flag)
#define SMEM_BYTES 105792

// ---------------- fused persistent kernel ----------------
__global__ void __launch_bounds__(256, 1)
k_all(const float* __restrict__ X,  const float* __restrict__ W1,
      const float* __restrict__ b1, const float* __restrict__ W2,
      const float* __restrict__ b2, const float* __restrict__ W3,
      const float* __restrict__ b3, const float* __restrict__ F1,
      const float* __restrict__ bf1, const float* __restrict__ F2,
      const float* __restrict__ bf2, float* __restrict__ out) {
    extern __shared__ char smem[];
    const uint32_t smb = smem_u32(smem);
    float* smf = reinterpret_cast<float*>(smem);
    int* sFlag = reinterpret_cast<int*>(smem + SM_FLAG);
    const int tid  = threadIdx.x;
    const int wid  = tid >> 5;
    const int lane = tid & 31;
    const int tig  = lane & 3;

    // ---- phase A: distributed layer-1 split ----
    for (int idx = tid; idx < 14 * 64; idx += 256) {
        int k = idx >> 6, c = idx & 63;
        int ng = blockIdx.x + GRID * k;
        if (ng < BATCH * NPTS) {
            float x0 = X[ng * 3 + 0], x1 = X[ng * 3 + 1], x2 = X[ng * 3 + 2];
            const float* w = W1 + c * 6;
            g_Aj[ng * 64 + c] = x0 * w[0] + x1 * w[1] + x2 * w[2];
            g_Ai[ng * 64 + c] = b1[c] + x0 * w[3] + x1 * w[4] + x2 * w[5];
        }
    }

    // ---- stage weights in [n][k] fp16 (contiguous reads; no transpose) ----
    for (int i2 = tid; i2 < 2048; i2 += 256) {           // W2: [64][64]
        int n = i2 >> 5, k2 = i2 & 31;
        *reinterpret_cast<uint32_t*>(smem + SM_W2 + n * 144 + k2 * 4) =
            cvt2h(W2[n * 64 + 2 * k2], W2[n * 64 + 2 * k2 + 1]);
    }
    for (int i2 = tid; i2 < 4096; i2 += 256) {           // W3: [128][64]
        int n = i2 >> 5, k2 = i2 & 31;
        *reinterpret_cast<uint32_t*>(smem + SM_W3 + n * 144 + k2 * 4) =
            cvt2h(W3[n * 64 + 2 * k2], W3[n * 64 + 2 * k2 + 1]);
    }
    if (tid < 64) smf[SM_B2 / 4 + tid] = b2[tid];

    // ---- grid barrier: all 148 CTAs co-resident (1 CTA/SM by smem) ----
    __threadfence();
    __syncthreads();
    if (tid == 0) {
        atomicAdd(&g_entry, 1u);
        while (*reinterpret_cast<volatile unsigned*>(&g_entry) < (unsigned)gridDim.x) { }
    }
    __syncthreads();

    // per-lane ldmatrix base addresses
    // A (non-trans, rows = H1 rows): rowset s at +s*128*144
    const int rowA = (wid << 4) + (lane & 7) + ((lane >> 3) & 1) * 8;
    const uint32_t aA0 = smb + SM_H1A + rowA * 144 + ((lane >> 4) << 4);
    const uint32_t aA1 = smb + SM_H1B + rowA * 144 + ((lane >> 4) << 4);
    // B (non-trans, rows = n): m0/m1 = n-octet 2p k-lo/hi, m2/m3 = octet 2p+1
    const int nPart = ((lane >> 4) & 1) * 8 + (lane & 7);
    const int kPart = ((lane >> 3) & 1) * 16;
    const uint32_t aW2 = smb + SM_W2 + nPart * 144 + kPart;
    const uint32_t aW3 = smb + SM_W3 + nPart * 144 + kPart;

    // ---- preload ALL W2 fragments into registers (persistent) ----
    uint32_t w2f[64];
#pragma unroll
    for (int kt = 0; kt < 4; kt++)
#pragma unroll
        for (int p = 0; p < 4; p++) {
            const int o = (kt * 4 + p) * 4;
            LDSM_X4(w2f[o], w2f[o + 1], w2f[o + 2], w2f[o + 3],
                    aW2 + p * (16 * 144) + kt * 32);
        }

    // H1 build indices: one full row (64 k) per thread
    const int b_il = tid >> 6;              // i_local 0..3
    const int b_jl = tid & 63;              // j_local

    auto build = [&](int tt, int hoff) {
        const int bb = tt >> 10, itt = (tt >> 3) & 127, jtt = tt & 7;
        const float4* ajp = reinterpret_cast<const float4*>(
            g_Aj + ((bb * NPTS + jtt * 64 + b_jl) * 64));
        const float4* aip = reinterpret_cast<const float4*>(
            g_Ai + ((bb * NPTS + itt * 4 + b_il) * 64));
        uint4* dh = reinterpret_cast<uint4*>(smem + hoff + tid * 144);
#pragma unroll
        for (int u = 0; u < 4; u++) {
            float4 a0 = ajp[4 * u + 0], i0 = aip[4 * u + 0];
            float4 a1 = ajp[4 * u + 1], i1 = aip[4 * u + 1];
            float4 a2v = ajp[4 * u + 2], i2v = aip[4 * u + 2];
            float4 a3 = ajp[4 * u + 3], i3 = aip[4 * u + 3];
            uint4 d;
            d.x = cvt2h(fmaxf(a0.x + i0.x, 0.f), fmaxf(a0.y + i0.y, 0.f));
            d.y = cvt2h(fmaxf(a0.z + i0.z, 0.f), fmaxf(a0.w + i0.w, 0.f));
            d.z = cvt2h(fmaxf(a1.x + i1.x, 0.f), fmaxf(a1.y + i1.y, 0.f));
            d.w = cvt2h(fmaxf(a1.z + i1.z, 0.f), fmaxf(a1.w + i1.w, 0.f));
            dh[2 * u] = d;
            uint4 e;
            e.x = cvt2h(fmaxf(a2v.x + i2v.x, 0.f), fmaxf(a2v.y + i2v.y, 0.f));
            e.y = cvt2h(fmaxf(a2v.z + i2v.z, 0.f), fmaxf(a2v.w + i2v.w, 0.f));
            e.z = cvt2h(fmaxf(a3.x + i3.x, 0.f), fmaxf(a3.y + i3.y, 0.f));
            e.w = cvt2h(fmaxf(a3.z + i3.z, 0.f), fmaxf(a3.w + i3.w, 0.f));
            dh[2 * u + 1] = e;
        }
    };

    float maxv[32];
#pragma unroll
    for (int q = 0; q < 32; q++) maxv[q] = -3.4e38f;
    int cur_b = -1;

    auto flush = [&](int bflush) {
#pragma unroll
        for (int q = 0; q < 32; q++) {
            float v = maxv[q];
            v = fmaxf(v, __shfl_xor_sync(0xffffffffu, v, 4));
            v = fmaxf(v, __shfl_xor_sync(0xffffffffu, v, 8));
            v = fmaxf(v, __shfl_xor_sync(0xffffffffu, v, 16));
            if (lane < 4)
                smf[SM_RED / 4 + wid * 128 + (q >> 1) * 8 + 2 * lane + (q & 1)] = v;
            maxv[q] = -3.4e38f;
        }
        __syncthreads();
        if (tid < 128) {
            float m = smf[SM_RED / 4 + tid];
#pragma unroll
            for (int w = 1; w < 8; w++) m = fmaxf(m, smf[SM_RED / 4 + w * 128 + tid]);
            g_part[(blockIdx.x * BATCH + bflush) * 128 + tid] = m;
        }
        __syncthreads();
    };

    // ---- prologue ----
    int t0 = blockIdx.x;
    if (t0 < NTILES) build(t0, SM_H1A);
    __syncthreads();                 // tile t0 H1 ready

    int buf = 0;
    for (int t = t0; t < NTILES; t += gridDim.x) {
        const int b = t >> 10;
        if (b != cur_b) {
            if (cur_b >= 0) flush(cur_b);
            cur_b = b;
        }

        // ---- load A1 fragments: 2 rowsets x 4 kt ----
        const uint32_t aA = buf ? aA1 : aA0;
        uint32_t a1[2][16];
#pragma unroll
        for (int s = 0; s < 2; s++)
#pragma unroll
            for (int kt = 0; kt < 4; kt++)
                LDSM_X4(a1[s][4 * kt], a1[s][4 * kt + 1], a1[s][4 * kt + 2], a1[s][4 * kt + 3],
                        aA + s * (128 * 144) + kt * 32);

        // ---- pipelined: build NEXT tile into the other buffer ----
        const int tn = t + gridDim.x;
        if (tn < NTILES) build(tn, buf ? SM_H1A : SM_H1B);

        // ---- GEMM1: C1 = H1 x W2^T; W2 frags already in registers ----
        float c1[2][8][4];
#pragma unroll
        for (int nt = 0; nt < 8; nt++) {
            float bl = smf[SM_B2 / 4 + nt * 8 + 2 * tig];
            float bh = smf[SM_B2 / 4 + nt * 8 + 2 * tig + 1];
#pragma unroll
            for (int s = 0; s < 2; s++) {
                c1[s][nt][0] = bl; c1[s][nt][1] = bh; c1[s][nt][2] = bl; c1[s][nt][3] = bh;
            }
        }
#pragma unroll
        for (int kt = 0; kt < 4; kt++) {
#pragma unroll
            for (int p = 0; p < 4; p++) {
                const int o = (kt * 4 + p) * 4;
#pragma unroll
                for (int s = 0; s < 2; s++) {
                    mma_f16(c1[s][2 * p],     &a1[s][4 * kt], w2f[o],     w2f[o + 1]);
                    mma_f16(c1[s][2 * p + 1], &a1[s][4 * kt], w2f[o + 2], w2f[o + 3]);
                }
            }
        }

        // ---- epilogue1: H2 = relu(C1); repack -> A2-frags ----
        uint32_t a2[2][16];
#pragma unroll
        for (int s = 0; s < 2; s++)
#pragma unroll
            for (int kt2 = 0; kt2 < 4; kt2++) {
                const int na = 2 * kt2, nb = 2 * kt2 + 1;
                a2[s][4 * kt2 + 0] = cvt2h(fmaxf(c1[s][na][0], 0.f), fmaxf(c1[s][na][1], 0.f));
                a2[s][4 * kt2 + 1] = cvt2h(fmaxf(c1[s][na][2], 0.f), fmaxf(c1[s][na][3], 0.f));
                a2[s][4 * kt2 + 2] = cvt2h(fmaxf(c1[s][nb][0], 0.f), fmaxf(c1[s][nb][1], 0.f));
                a2[s][4 * kt2 + 3] = cvt2h(fmaxf(c1[s][nb][2], 0.f), fmaxf(c1[s][nb][3], 0.f));
            }

        // ---- GEMM2: D3 = H2 x W3^T, two n-halves; non-trans weight loads ----
#pragma unroll
        for (int h = 0; h < 2; h++) {
            float d3[2][8][4];
#pragma unroll
            for (int s = 0; s < 2; s++)
#pragma unroll
                for (int nt = 0; nt < 8; nt++)
#pragma unroll
                    for (int q = 0; q < 4; q++) d3[s][nt][q] = 0.f;
#pragma unroll
            for (int kt2 = 0; kt2 < 4; kt2++) {
#pragma unroll
                for (int p = 0; p < 4; p++) {
                    uint32_t bh0, bh1, bh2, bh3;
                    LDSM_X4(bh0, bh1, bh2, bh3,
                            aW3 + (h * 4 + p) * (16 * 144) + kt2 * 32);
#pragma unroll
                    for (int s = 0; s < 2; s++) {
                        mma_f16(d3[s][2 * p],     &a2[s][4 * kt2], bh0, bh1);
                        mma_f16(d3[s][2 * p + 1], &a2[s][4 * kt2], bh2, bh3);
                    }
                }
            }
#pragma unroll
            for (int nt = 0; nt < 8; nt++) {
                float m0 = fmaxf(fmaxf(d3[0][nt][0], d3[0][nt][2]),
                                 fmaxf(d3[1][nt][0], d3[1][nt][2]));
                float m1 = fmaxf(fmaxf(d3[0][nt][1], d3[0][nt][3]),
                                 fmaxf(d3[1][nt][1], d3[1][nt][3]));
                maxv[h * 16 + 2 * nt]     = fmaxf(maxv[h * 16 + 2 * nt],     m0);
                maxv[h * 16 + 2 * nt + 1] = fmaxf(maxv[h * 16 + 2 * nt + 1], m1);
            }
        }

        __syncthreads();
        buf ^= 1;
    }
    flush(cur_b);                    // every CTA has tiles in every batch; cur_b >= 0

    // ---- completion: last CTA reduces partials + head MLP ----
    __threadfence();
    __syncthreads();
    if (tid == 0) sFlag[0] = (atomicAdd(&g_done, 1u) == (unsigned)gridDim.x - 1) ? 1 : 0;
    __syncthreads();

    if (sFlag[0]) {
        __threadfence();
        for (int pair = tid; pair < BATCH * 128; pair += 256) {
            int bb = pair >> 7, ch = pair & 127;
            float m = -3.4e38f;
            for (int c = 0; c < (int)gridDim.x; c++)
                m = fmaxf(m, g_part[(c * BATCH + bb) * 128 + ch]);
            smf[SM_RED / 4 + pair] = m + b3[ch];
        }
        __syncthreads();
        float* st = smf + SM_RED / 4 + 512;
        for (int bb = 0; bb < BATCH; bb++) {
            const int r = tid >> 2, q = tid & 3;
            float a = 0.f;
            const float* fr = F1 + r * 128 + q * 32;
            const float* spb = smf + SM_RED / 4 + bb * 128 + q * 32;
#pragma unroll 8
            for (int c = 0; c < 32; c++) a += fr[c] * spb[c];
            a += __shfl_xor_sync(0xffffffffu, a, 1);
            a += __shfl_xor_sync(0xffffffffu, a, 2);
            if (q == 0) st[r] = fmaxf(a + bf1[r], 0.f);
            __syncthreads();
            if (tid < 2) {
                float acc = bf2[tid];
#pragma unroll
                for (int j = 0; j < 64; j++) acc += F2[tid * 64 + j] * st[j];
                out[bb * 2 + tid] = acc;
            }
            __syncthreads();
        }
        if (tid == 0) { g_done = 0; g_entry = 0; __threadfence(); }
    }
}

// ---------------- launch ----------------
extern "C" void kernel_launch(void* const* d_in, const int* in_sizes, int n_in,
                              void* d_out, int out_size) {
    const float* X   = (const float*)d_in[0];
    const float* W1  = (const float*)d_in[1];
    const float* b1  = (const float*)d_in[2];
    const float* W2  = (const float*)d_in[3];
    const float* b2  = (const float*)d_in[4];
    const float* W3  = (const float*)d_in[5];
    const float* b3  = (const float*)d_in[6];
    const float* F1  = (const float*)d_in[7];
    const float* bf1 = (const float*)d_in[8];
    const float* F2  = (const float*)d_in[9];
    const float* bf2 = (const float*)d_in[10];
    float* out = (float*)d_out;

    cudaFuncSetAttribute(k_all, cudaFuncAttributeMaxDynamicSharedMemorySize, SMEM_BYTES);

    k_all<<<GRID, 256, SMEM_BYTES>>>(X, W1, b1, W2, b2, W3,
                                     b3, F1, bf1, F2, bf2, out);
}

// round 17
// speedup vs baseline: 1.3300x; 1.2822x over previous
#include <cuda_runtime.h>
#include <cuda_fp16.h>
#include <cstdint>

// PointPairNet: B=4, N=512, D=3. pair-relu(64) -> 64 -> 128, global max-pool, head MLP.
// R16: fp16 g_Ai/g_Aj storage (HADD2 build) + GEMM1 f16 accumulators (bias-in-init,
// HMAX2 epilogue, zero repack). GEMM2 fp32 accum. Fused persistent kernel.

#define BATCH 4
#define NPTS  512
#define GRID  148
#define NTILES 4096         // 256-pair tiles: 4 batches x 128 i-groups x 8 j-groups

__device__ __half   g_AiH[BATCH * NPTS * 64];
__device__ __half   g_AjH[BATCH * NPTS * 64];
__device__ float    g_part[GRID * BATCH * 128];   // per-CTA partial maxes (rewritten per call)
__device__ unsigned g_entry;                       // grid barrier counter (reset by last CTA)
__device__ unsigned g_done;                        // completion counter  (reset by last CTA)

// ---------------- helpers ----------------
static __device__ __forceinline__ uint32_t smem_u32(const void* p) {
    uint32_t a;
    asm("{ .reg .u64 t; cvta.to.shared.u64 t, %1; cvt.u32.u64 %0, t; }" : "=r"(a) : "l"(p));
    return a;
}
static __device__ __forceinline__ uint32_t cvt2h(float f0, float f1) {
    __half2 h = __floats2half2_rn(f0, f1);
    return *reinterpret_cast<uint32_t*>(&h);
}
static __device__ __forceinline__ uint32_t hrelu_add(uint32_t a, uint32_t b) {
    __half2 ha = *reinterpret_cast<__half2*>(&a);
    __half2 hb = *reinterpret_cast<__half2*>(&b);
    __half2 r = __hmax2(__hadd2(ha, hb), __float2half2_rn(0.f));
    return *reinterpret_cast<uint32_t*>(&r);
}
static __device__ __forceinline__ uint32_t hrelu(uint32_t a) {
    __half2 ha = *reinterpret_cast<__half2*>(&a);
    __half2 r = __hmax2(ha, __float2half2_rn(0.f));
    return *reinterpret_cast<uint32_t*>(&r);
}

#define LDSM_X4(r0, r1, r2, r3, a)                                                  \
    asm volatile("ldmatrix.sync.aligned.m8n8.x4.shared.b16 {%0,%1,%2,%3}, [%4];"    \
                 : "=r"(r0), "=r"(r1), "=r"(r2), "=r"(r3) : "r"(a))

static __device__ __forceinline__ void mma_f16(float* c, const uint32_t* a,
                                               uint32_t b0, uint32_t b1) {
    asm volatile("mma.sync.aligned.m16n8k16.row.col.f32.f16.f16.f32 "
                 "{%0,%1,%2,%3}, {%4,%5,%6,%7}, {%8,%9}, {%0,%1,%2,%3};"
                 : "+f"(c[0]), "+f"(c[1]), "+f"(c[2]), "+f"(c[3])
                 : "r"(a[0]), "r"(a[1]), "r"(a[2]), "r"(a[3]), "r"(b0), "r"(b1));
}
// f16 accumulators: D,C are 2 packed-half2 regs
static __device__ __forceinline__ void mma_f16h(uint32_t* d, const uint32_t* a,
                                                uint32_t b0, uint32_t b1) {
    asm volatile("mma.sync.aligned.m16n8k16.row.col.f16.f16.f16.f16 "
                 "{%0,%1}, {%2,%3,%4,%5}, {%6,%7}, {%0,%1};"
                 : "+r"(d[0]), "+r"(d[1])
                 : "r"(a[0]), "r"(a[1]), "r"(a[2]), "r"(a[3]), "r"(b0), "r"(b1));
}

// ---------------- SMEM layout (bytes) ----------------
// All weight/activation rows stride 144 B (16B-aligned, conflict-free 8-row ldmatrix).
#define SM_B2    0          // 64 floats (256B)
#define SM_W2    256        // [n=64][k=64] fp16, stride 144 -> 9216
#define SM_W3    9472       // [n=128][k=64] fp16, stride 144 -> 18432
#define SM_H1A   27904      // [row=256][k=64] fp16, stride 144 -> 36864 (buffer 0)
#define SM_H1B   64768      // buffer 1
#define SM_RED   101632     // flush scratch: 8 warps x 128 floats = 4096 B (tail reuses)
#define SM_FLAG  105728     // 64 B (last-CTA flag)
#define SMEM_BYTES 105792

// ---------------- fused persistent kernel ----------------
__global__ void __launch_bounds__(256, 1)
k_all(const float* __restrict__ X,  const float* __restrict__ W1,
      const float* __restrict__ b1, const float* __restrict__ W2,
      const float* __restrict__ b2, const float* __restrict__ W3,
      const float* __restrict__ b3, const float* __restrict__ F1,
      const float* __restrict__ bf1, const float* __restrict__ F2,
      const float* __restrict__ bf2, float* __restrict__ out) {
    extern __shared__ char smem[];
    const uint32_t smb = smem_u32(smem);
    float* smf = reinterpret_cast<float*>(smem);
    int* sFlag = reinterpret_cast<int*>(smem + SM_FLAG);
    const int tid  = threadIdx.x;
    const int wid  = tid >> 5;
    const int lane = tid & 31;
    const int tig  = lane & 3;

    // ---- phase A: distributed layer-1 split -> fp16 ----
    for (int idx = tid; idx < 14 * 64; idx += 256) {
        int k = idx >> 6, c = idx & 63;
        int ng = blockIdx.x + GRID * k;
        if (ng < BATCH * NPTS) {
            float x0 = X[ng * 3 + 0], x1 = X[ng * 3 + 1], x2 = X[ng * 3 + 2];
            const float* w = W1 + c * 6;
            g_AjH[ng * 64 + c] = __float2half(x0 * w[0] + x1 * w[1] + x2 * w[2]);
            g_AiH[ng * 64 + c] = __float2half(b1[c] + x0 * w[3] + x1 * w[4] + x2 * w[5]);
        }
    }

    // ---- stage weights in [n][k] fp16 (non-trans B-frag layout) ----
    for (int i2 = tid; i2 < 2048; i2 += 256) {           // W2: [64][64]
        int n = i2 >> 5, k2 = i2 & 31;
        *reinterpret_cast<uint32_t*>(smem + SM_W2 + n * 144 + k2 * 4) =
            cvt2h(W2[n * 64 + 2 * k2], W2[n * 64 + 2 * k2 + 1]);
    }
    for (int i2 = tid; i2 < 4096; i2 += 256) {           // W3: [128][64]
        int n = i2 >> 5, k2 = i2 & 31;
        *reinterpret_cast<uint32_t*>(smem + SM_W3 + n * 144 + k2 * 4) =
            cvt2h(W3[n * 64 + 2 * k2], W3[n * 64 + 2 * k2 + 1]);
    }
    if (tid < 64) smf[SM_B2 / 4 + tid] = b2[tid];

    // ---- grid barrier: all 148 CTAs co-resident (1 CTA/SM by smem) ----
    __threadfence();
    __syncthreads();
    if (tid == 0) {
        atomicAdd(&g_entry, 1u);
        while (*reinterpret_cast<volatile unsigned*>(&g_entry) < (unsigned)gridDim.x) { }
    }
    __syncthreads();

    // bias as packed half2 per n-octet (C-frag cols 8nt+2tig, +1)
    uint32_t bc2[8];
#pragma unroll
    for (int nt = 0; nt < 8; nt++)
        bc2[nt] = cvt2h(smf[SM_B2 / 4 + nt * 8 + 2 * tig],
                        smf[SM_B2 / 4 + nt * 8 + 2 * tig + 1]);

    // per-lane ldmatrix base addresses
    const int rowA = (wid << 4) + (lane & 7) + ((lane >> 3) & 1) * 8;
    const uint32_t aA0 = smb + SM_H1A + rowA * 144 + ((lane >> 4) << 4);
    const uint32_t aA1 = smb + SM_H1B + rowA * 144 + ((lane >> 4) << 4);
    const int nPart = ((lane >> 4) & 1) * 8 + (lane & 7);
    const int kPart = ((lane >> 3) & 1) * 16;
    const uint32_t aW2 = smb + SM_W2 + nPart * 144 + kPart;
    const uint32_t aW3 = smb + SM_W3 + nPart * 144 + kPart;

    // ---- preload ALL W2 fragments into registers (persistent) ----
    uint32_t w2f[64];
#pragma unroll
    for (int kt = 0; kt < 4; kt++)
#pragma unroll
        for (int p = 0; p < 4; p++) {
            const int o = (kt * 4 + p) * 4;
            LDSM_X4(w2f[o], w2f[o + 1], w2f[o + 2], w2f[o + 3],
                    aW2 + p * (16 * 144) + kt * 32);
        }

    // H1 build indices: one full row (64 k) per thread
    const int b_il = tid >> 6;              // i_local 0..3
    const int b_jl = tid & 63;              // j_local

    auto build = [&](int tt, int hoff) {
        const int bb = tt >> 10, itt = (tt >> 3) & 127, jtt = tt & 7;
        const uint4* ajp = reinterpret_cast<const uint4*>(
            g_AjH + ((bb * NPTS + jtt * 64 + b_jl) * 64));
        const uint4* aip = reinterpret_cast<const uint4*>(
            g_AiH + ((bb * NPTS + itt * 4 + b_il) * 64));
        uint4* dh = reinterpret_cast<uint4*>(smem + hoff + tid * 144);
#pragma unroll
        for (int u = 0; u < 8; u++) {
            uint4 a = ajp[u], i = aip[u];
            uint4 d;
            d.x = hrelu_add(a.x, i.x);
            d.y = hrelu_add(a.y, i.y);
            d.z = hrelu_add(a.z, i.z);
            d.w = hrelu_add(a.w, i.w);
            dh[u] = d;
        }
    };

    float maxv[32];
#pragma unroll
    for (int q = 0; q < 32; q++) maxv[q] = -3.4e38f;
    int cur_b = -1;

    auto flush = [&](int bflush) {
#pragma unroll
        for (int q = 0; q < 32; q++) {
            float v = maxv[q];
            v = fmaxf(v, __shfl_xor_sync(0xffffffffu, v, 4));
            v = fmaxf(v, __shfl_xor_sync(0xffffffffu, v, 8));
            v = fmaxf(v, __shfl_xor_sync(0xffffffffu, v, 16));
            if (lane < 4)
                smf[SM_RED / 4 + wid * 128 + (q >> 1) * 8 + 2 * lane + (q & 1)] = v;
            maxv[q] = -3.4e38f;
        }
        __syncthreads();
        if (tid < 128) {
            float m = smf[SM_RED / 4 + tid];
#pragma unroll
            for (int w = 1; w < 8; w++) m = fmaxf(m, smf[SM_RED / 4 + w * 128 + tid]);
            g_part[(blockIdx.x * BATCH + bflush) * 128 + tid] = m;
        }
        __syncthreads();
    };

    // ---- prologue ----
    int t0 = blockIdx.x;
    if (t0 < NTILES) build(t0, SM_H1A);
    __syncthreads();                 // tile t0 H1 ready

    int buf = 0;
    for (int t = t0; t < NTILES; t += gridDim.x) {
        const int b = t >> 10;
        if (b != cur_b) {
            if (cur_b >= 0) flush(cur_b);
            cur_b = b;
        }

        // ---- load A1 fragments: 2 rowsets x 4 kt ----
        const uint32_t aA = buf ? aA1 : aA0;
        uint32_t a1[2][16];
#pragma unroll
        for (int s = 0; s < 2; s++)
#pragma unroll
            for (int kt = 0; kt < 4; kt++)
                LDSM_X4(a1[s][4 * kt], a1[s][4 * kt + 1], a1[s][4 * kt + 2], a1[s][4 * kt + 3],
                        aA + s * (128 * 144) + kt * 32);

        // ---- pipelined: build NEXT tile into the other buffer ----
        const int tn = t + gridDim.x;
        if (tn < NTILES) build(tn, buf ? SM_H1A : SM_H1B);

        // ---- GEMM1 (f16 accum): C1 = H1 x W2^T + b2; W2 frags in registers ----
        // c1h[s][4kt2+j] doubles as GEMM2 A-frag after in-place relu.
        uint32_t c1h[2][16];
#pragma unroll
        for (int nt = 0; nt < 8; nt++)
#pragma unroll
            for (int s = 0; s < 2; s++) {
                c1h[s][2 * nt]     = bc2[nt];
                c1h[s][2 * nt + 1] = bc2[nt];
            }
#pragma unroll
        for (int kt = 0; kt < 4; kt++) {
#pragma unroll
            for (int p = 0; p < 4; p++) {
                const int o = (kt * 4 + p) * 4;
#pragma unroll
                for (int s = 0; s < 2; s++) {
                    mma_f16h(&c1h[s][2 * (2 * p)],     &a1[s][4 * kt], w2f[o],     w2f[o + 1]);
                    mma_f16h(&c1h[s][2 * (2 * p + 1)], &a1[s][4 * kt], w2f[o + 2], w2f[o + 3]);
                }
            }
        }

        // ---- epilogue1: in-place relu; c1h becomes A2-frags directly ----
#pragma unroll
        for (int s = 0; s < 2; s++)
#pragma unroll
            for (int j = 0; j < 16; j++) c1h[s][j] = hrelu(c1h[s][j]);

        // ---- GEMM2 (fp32 accum): D3 = H2 x W3^T, two n-halves ----
#pragma unroll
        for (int h = 0; h < 2; h++) {
            float d3[2][8][4];
#pragma unroll
            for (int s = 0; s < 2; s++)
#pragma unroll
                for (int nt = 0; nt < 8; nt++)
#pragma unroll
                    for (int q = 0; q < 4; q++) d3[s][nt][q] = 0.f;
#pragma unroll
            for (int kt2 = 0; kt2 < 4; kt2++) {
#pragma unroll
                for (int p = 0; p < 4; p++) {
                    uint32_t bh0, bh1, bh2, bh3;
                    LDSM_X4(bh0, bh1, bh2, bh3,
                            aW3 + (h * 4 + p) * (16 * 144) + kt2 * 32);
#pragma unroll
                    for (int s = 0; s < 2; s++) {
                        mma_f16(d3[s][2 * p],     &c1h[s][4 * kt2], bh0, bh1);
                        mma_f16(d3[s][2 * p + 1], &c1h[s][4 * kt2], bh2, bh3);
                    }
                }
            }
#pragma unroll
            for (int nt = 0; nt < 8; nt++) {
                float m0 = fmaxf(fmaxf(d3[0][nt][0], d3[0][nt][2]),
                                 fmaxf(d3[1][nt][0], d3[1][nt][2]));
                float m1 = fmaxf(fmaxf(d3[0][nt][1], d3[0][nt][3]),
                                 fmaxf(d3[1][nt][1], d3[1][nt][3]));
                maxv[h * 16 + 2 * nt]     = fmaxf(maxv[h * 16 + 2 * nt],     m0);
                maxv[h * 16 + 2 * nt + 1] = fmaxf(maxv[h * 16 + 2 * nt + 1], m1);
            }
        }

        __syncthreads();
        buf ^= 1;
    }
    flush(cur_b);                    // every CTA has tiles in every batch; cur_b >= 0

    // ---- completion: last CTA reduces partials + head MLP ----
    __threadfence();
    __syncthreads();
    if (tid == 0) sFlag[0] = (atomicAdd(&g_done, 1u) == (unsigned)gridDim.x - 1) ? 1 : 0;
    __syncthreads();

    if (sFlag[0]) {
        __threadfence();
        for (int pair = tid; pair < BATCH * 128; pair += 256) {
            int bb = pair >> 7, ch = pair & 127;
            float m = -3.4e38f;
            for (int c = 0; c < (int)gridDim.x; c++)
                m = fmaxf(m, g_part[(c * BATCH + bb) * 128 + ch]);
            smf[SM_RED / 4 + pair] = m + b3[ch];
        }
        __syncthreads();
        float* st = smf + SM_RED / 4 + 512;
        for (int bb = 0; bb < BATCH; bb++) {
            const int r = tid >> 2, q = tid & 3;
            float a = 0.f;
            const float* fr = F1 + r * 128 + q * 32;
            const float* spb = smf + SM_RED / 4 + bb * 128 + q * 32;
#pragma unroll 8
            for (int c = 0; c < 32; c++) a += fr[c] * spb[c];
            a += __shfl_xor_sync(0xffffffffu, a, 1);
            a += __shfl_xor_sync(0xffffffffu, a, 2);
            if (q == 0) st[r] = fmaxf(a + bf1[r], 0.f);
            __syncthreads();
            if (tid < 2) {
                float acc = bf2[tid];
#pragma unroll
                for (int j = 0; j < 64; j++) acc += F2[tid * 64 + j] * st[j];
                out[bb * 2 + tid] = acc;
            }
            __syncthreads();
        }
        if (tid == 0) { g_done = 0; g_entry = 0; __threadfence(); }
    }
}

// ---------------- launch ----------------
extern "C" void kernel_launch(void* const* d_in, const int* in_sizes, int n_in,
                              void* d_out, int out_size) {
    const float* X   = (const float*)d_in[0];
    const float* W1  = (const float*)d_in[1];
    const float* b1  = (const float*)d_in[2];
    const float* W2  = (const float*)d_in[3];
    const float* b2  = (const float*)d_in[4];
    const float* W3  = (const float*)d_in[5];
    const float* b3  = (const float*)d_in[6];
    const float* F1  = (const float*)d_in[7];
    const float* bf1 = (const float*)d_in[8];
    const float* F2  = (const float*)d_in[9];
    const float* bf2 = (const float*)d_in[10];
    float* out = (float*)d_out;

    cudaFuncSetAttribute(k_all, cudaFuncAttributeMaxDynamicSharedMemorySize, SMEM_BYTES);

    k_all<<<GRID, 256, SMEM_BYTES>>>(X, W1, b1, W2, b2, W3,
                                     b3, F1, bf1, F2, bf2, out);
}